// round 2
// baseline (speedup 1.0000x reference)
#include <cuda_runtime.h>
#include <cuda_bf16.h>

#define N_NODES 50000
#define N_EDGES 800000
#define HIDDEN 128
#define NUM_GRAPHS 64
#define NUM_CLASSES 6

// ---- scratch (static device globals; no runtime allocation) ----
__device__ float g_hw[N_NODES * HIDDEN];    // h @ W
__device__ float g_agg[N_NODES * HIDDEN];   // aggregation accumulator
__device__ float g_h[N_NODES * HIDDEN];     // layer activation
__device__ float g_dinv[N_NODES];
__device__ int   g_deg[N_NODES];
__device__ float g_pool[NUM_GRAPHS * HIDDEN];
__device__ float g_cnt[NUM_GRAPHS];

// ---- init / degree ----
__global__ void k_zero() {
    int i = blockIdx.x * blockDim.x + threadIdx.x;
    if (i < N_NODES) g_deg[i] = 0;
    if (i < NUM_GRAPHS * HIDDEN) g_pool[i] = 0.f;
    if (i < NUM_GRAPHS) g_cnt[i] = 0.f;
}

__global__ void k_deg(const int* __restrict__ dst) {
    int e = blockIdx.x * blockDim.x + threadIdx.x;
    if (e < N_EDGES) atomicAdd(&g_deg[dst[e]], 1);
}

__global__ void k_dinv() {
    int i = blockIdx.x * blockDim.x + threadIdx.x;
    if (i < N_NODES) g_dinv[i] = rsqrtf((float)(g_deg[i] + 1));  // +1 self-loop
}

// ---- dense projection: hw = A @ W  (A is [N,128] row-major, W is [128,128]) ----
#define GEMM_ROWS 16
__global__ void k_gemm(const float* __restrict__ A, const float* __restrict__ W) {
    if (A == nullptr) A = g_h;   // layers 1,2 read previous activation
    __shared__ float shA[GEMM_ROWS][HIDDEN];
    int row0 = blockIdx.x * GEMM_ROWS;
    int t = threadIdx.x;  // 0..127, output column
#pragma unroll
    for (int r = 0; r < GEMM_ROWS; r++)
        shA[r][t] = A[(size_t)(row0 + r) * HIDDEN + t];
    __syncthreads();
    float acc[GEMM_ROWS];
#pragma unroll
    for (int r = 0; r < GEMM_ROWS; r++) acc[r] = 0.f;
    for (int k = 0; k < HIDDEN; k++) {
        float w = __ldg(&W[k * HIDDEN + t]);
#pragma unroll
        for (int r = 0; r < GEMM_ROWS; r++)
            acc[r] += shA[r][k] * w;
    }
#pragma unroll
    for (int r = 0; r < GEMM_ROWS; r++)
        g_hw[(size_t)(row0 + r) * HIDDEN + t] = acc[r];
}

// ---- agg init: self-loop contribution (norm = dinv[n]^2) ----
__global__ void k_initagg() {
    int i = blockIdx.x * blockDim.x + threadIdx.x;
    if (i < N_NODES * HIDDEN) {
        float dv = g_dinv[i >> 7];
        g_agg[i] = dv * dv * g_hw[i];
    }
}

// ---- edge scatter: one warp per edge, float4 gather, 4 atomics/lane ----
__global__ void k_scatter(const int* __restrict__ src,
                          const int* __restrict__ dst) {
    int e = blockIdx.x * (blockDim.x >> 5) + (threadIdx.x >> 5);
    if (e >= N_EDGES) return;
    int lane = threadIdx.x & 31;
    int s = src[e];
    int d = dst[e];
    float w = g_dinv[s] * g_dinv[d];
    float4 v = ((const float4*)(g_hw + (size_t)s * HIDDEN))[lane];
    float* ag = g_agg + (size_t)d * HIDDEN + lane * 4;
    atomicAdd(ag + 0, w * v.x);
    atomicAdd(ag + 1, w * v.y);
    atomicAdd(ag + 2, w * v.z);
    atomicAdd(ag + 3, w * v.w);
}

// ---- bias + relu ----
__global__ void k_relu(const float* __restrict__ b) {
    int i = blockIdx.x * blockDim.x + threadIdx.x;
    if (i < N_NODES * HIDDEN)
        g_h[i] = fmaxf(g_agg[i] + b[i & 127], 0.f);
}

// ---- pooling: run-length accumulate over sorted batch ids ----
#define NODES_PER_BLOCK 32
__global__ void k_pool(const int* __restrict__ batch) {
    int n0 = blockIdx.x * NODES_PER_BLOCK;
    if (n0 >= N_NODES) return;
    int t = threadIdx.x;  // 0..127 col
    int cur = batch[n0];
    float acc = 0.f;
    int run = 0;
    for (int r = 0; r < NODES_PER_BLOCK; r++) {
        int n = n0 + r;
        if (n >= N_NODES) break;
        int bg = batch[n];
        if (bg != cur) {
            atomicAdd(&g_pool[cur * HIDDEN + t], acc);
            if (t == 0) atomicAdd(&g_cnt[cur], (float)run);
            acc = 0.f; run = 0; cur = bg;
        }
        acc += g_h[(size_t)n * HIDDEN + t];
        run++;
    }
    atomicAdd(&g_pool[cur * HIDDEN + t], acc);
    if (t == 0) atomicAdd(&g_cnt[cur], (float)run);
}

// ---- mean + linear head, write outputs ----
__global__ void k_final(const float* __restrict__ linW, const float* __restrict__ linb,
                        float* __restrict__ out, int emb_off,
                        int write_emb, int write_logits) {
    int g = blockIdx.x;
    int t = threadIdx.x;  // 128
    float c = fmaxf(g_cnt[g], 1.f);
    float e = g_pool[g * HIDDEN + t] / c;
    __shared__ float se[HIDDEN];
    se[t] = e;
    if (write_emb) out[emb_off + g * HIDDEN + t] = e;
    __syncthreads();
    if (write_logits && t < NUM_CLASSES) {
        float acc = linb[t];
#pragma unroll 16
        for (int k = 0; k < HIDDEN; k++)
            acc += se[k] * linW[k * NUM_CLASSES + t];
        out[g * NUM_CLASSES + t] = acc;
    }
}

extern "C" void kernel_launch(void* const* d_in, const int* in_sizes, int n_in,
                              void* d_out, int out_size) {
    const float* x     = (const float*)d_in[0];
    const int*   ei    = (const int*)d_in[1];   // [2, E] (JAX x64 off -> int32)
    const int*   batch = (const int*)d_in[2];
    const float* W0 = (const float*)d_in[3];
    const float* b0 = (const float*)d_in[4];
    const float* W1 = (const float*)d_in[5];
    const float* b1 = (const float*)d_in[6];
    const float* W2 = (const float*)d_in[7];
    const float* b2 = (const float*)d_in[8];
    const float* linW = (const float*)d_in[9];
    const float* linb = (const float*)d_in[10];
    float* out = (float*)d_out;

    const int* src = ei;            // edge_index[0]
    const int* dst = ei + N_EDGES;  // edge_index[1]

    k_zero<<<(N_NODES + 255) / 256, 256>>>();
    k_deg<<<(N_EDGES + 255) / 256, 256>>>(dst);
    k_dinv<<<(N_NODES + 255) / 256, 256>>>();

    const float* Ws[3] = {W0, W1, W2};
    const float* bs[3] = {b0, b1, b2};

    const int nh = N_NODES * HIDDEN;
    const int gemm_grid = N_NODES / GEMM_ROWS;          // 50000/16 = 3125 exact
    const int scat_grid = (N_EDGES + 7) / 8;            // 8 edges/block @ 256 thr

    for (int l = 0; l < 3; l++) {
        const float* A = (l == 0) ? x : nullptr;        // nullptr -> g_h inside
        k_gemm<<<gemm_grid, HIDDEN>>>(A, Ws[l]);
        k_initagg<<<(nh + 255) / 256, 256>>>();
        k_scatter<<<scat_grid, 256>>>(src, dst);
        k_relu<<<(nh + 255) / 256, 256>>>(bs[l]);
    }

    k_pool<<<(N_NODES + NODES_PER_BLOCK - 1) / NODES_PER_BLOCK, HIDDEN>>>(batch);

    // Output: reference returns (logits[64,6], embedding[64,128]) -> 8576 floats.
    int write_logits = 1, write_emb = 0, emb_off = 0;
    if (out_size >= NUM_GRAPHS * (NUM_CLASSES + HIDDEN)) {
        write_emb = 1; emb_off = NUM_GRAPHS * NUM_CLASSES;
    } else if (out_size == NUM_GRAPHS * HIDDEN) {
        write_emb = 1; write_logits = 0; emb_off = 0;
    }
    k_final<<<NUM_GRAPHS, HIDDEN>>>(linW, linb, out, emb_off, write_emb, write_logits);
}

// round 4
// speedup vs baseline: 2.2237x; 2.2237x over previous
#include <cuda_runtime.h>
#include <cuda_bf16.h>

#define N_NODES 50000
#define N_EDGES 800000
#define HIDDEN 128
#define NUM_GRAPHS 64
#define NUM_CLASSES 6

// ---- scratch (static device globals; no runtime allocation) ----
__device__ float g_hw[N_NODES * HIDDEN];     // h @ W
__device__ float g_h[N_NODES * HIDDEN];      // layer activation
__device__ float g_dinv[N_NODES];
__device__ int   g_deg[N_NODES];
__device__ int   g_rowptr[N_NODES + 1];
__device__ int   g_cursor[N_NODES];
__device__ int   g_csr_src[N_EDGES];
__device__ float g_csr_w[N_EDGES];
__device__ float g_pool[NUM_GRAPHS * HIDDEN];
__device__ float g_cnt[NUM_GRAPHS];

// ---- init ----
__global__ void k_zero() {
    int i = blockIdx.x * blockDim.x + threadIdx.x;
    if (i < N_NODES) g_deg[i] = 0;
    if (i < NUM_GRAPHS * HIDDEN) g_pool[i] = 0.f;
    if (i < NUM_GRAPHS) g_cnt[i] = 0.f;
}

__global__ void k_deg(const int* __restrict__ dst) {
    int e = blockIdx.x * blockDim.x + threadIdx.x;
    if (e < N_EDGES) atomicAdd(&g_deg[dst[e]], 1);
}

__global__ void k_dinv() {
    int i = blockIdx.x * blockDim.x + threadIdx.x;
    if (i < N_NODES) g_dinv[i] = rsqrtf((float)(g_deg[i] + 1));  // +1 self-loop
}

// ---- single-block exclusive scan of g_deg -> g_rowptr (and cursor init) ----
__global__ void k_scan() {
    __shared__ int warp_sums[32];
    __shared__ int s_carry;
    int lane = threadIdx.x & 31;
    int wid = threadIdx.x >> 5;
    if (threadIdx.x == 0) s_carry = 0;
    __syncthreads();
    for (int base = 0; base < N_NODES; base += 1024) {
        int i = base + threadIdx.x;
        int v = (i < N_NODES) ? g_deg[i] : 0;
        int x = v;
#pragma unroll
        for (int o = 1; o < 32; o <<= 1) {
            int y = __shfl_up_sync(0xffffffffu, x, o);
            if (lane >= o) x += y;
        }
        if (lane == 31) warp_sums[wid] = x;
        __syncthreads();
        if (wid == 0) {
            int s = warp_sums[lane];
#pragma unroll
            for (int o = 1; o < 32; o <<= 1) {
                int y = __shfl_up_sync(0xffffffffu, s, o);
                if (lane >= o) s += y;
            }
            warp_sums[lane] = s;
        }
        __syncthreads();
        int excl = (x - v) + (wid > 0 ? warp_sums[wid - 1] : 0) + s_carry;
        if (i < N_NODES) { g_rowptr[i] = excl; g_cursor[i] = excl; }
        __syncthreads();
        if (threadIdx.x == 1023) s_carry = excl + v;
        __syncthreads();
    }
    if (threadIdx.x == 0) g_rowptr[N_NODES] = N_EDGES;
}

// ---- fill CSR (src index + edge weight), bucketed by dst ----
__global__ void k_fill(const int* __restrict__ src, const int* __restrict__ dst) {
    int e = blockIdx.x * blockDim.x + threadIdx.x;
    if (e >= N_EDGES) return;
    int s = src[e];
    int d = dst[e];
    int pos = atomicAdd(&g_cursor[d], 1);
    g_csr_src[pos] = s;
    g_csr_w[pos] = g_dinv[s] * g_dinv[d];
}

// ---- dense projection: hw = A @ W  (A [N,128] row-major, W [128,128]) ----
#define GEMM_ROWS 16
__global__ void k_gemm(const float* __restrict__ A, const float* __restrict__ W) {
    if (A == nullptr) A = g_h;   // layers 1,2 read previous activation
    __shared__ float4 shA[GEMM_ROWS][HIDDEN / 4];   // 8 KB
    int row0 = blockIdx.x * GEMM_ROWS;
    int t = threadIdx.x;  // 0..127, output column
    const float4* Af = (const float4*)(A + (size_t)row0 * HIDDEN);
    float4* shf = &shA[0][0];
#pragma unroll
    for (int i = 0; i < 4; i++)
        shf[i * 128 + t] = Af[i * 128 + t];
    __syncthreads();
    float acc[GEMM_ROWS];
#pragma unroll
    for (int r = 0; r < GEMM_ROWS; r++) acc[r] = 0.f;
#pragma unroll 4
    for (int k4 = 0; k4 < HIDDEN / 4; k4++) {
        float w0 = __ldg(&W[(k4 * 4 + 0) * HIDDEN + t]);
        float w1 = __ldg(&W[(k4 * 4 + 1) * HIDDEN + t]);
        float w2 = __ldg(&W[(k4 * 4 + 2) * HIDDEN + t]);
        float w3 = __ldg(&W[(k4 * 4 + 3) * HIDDEN + t]);
#pragma unroll
        for (int r = 0; r < GEMM_ROWS; r++) {
            float4 a = shA[r][k4];
            acc[r] += a.x * w0 + a.y * w1 + a.z * w2 + a.w * w3;
        }
    }
#pragma unroll
    for (int r = 0; r < GEMM_ROWS; r++)
        g_hw[(size_t)(row0 + r) * HIDDEN + t] = acc[r];
}

// ---- fused aggregate (CSR gather) + self-loop + bias + ReLU ----
__global__ void k_agg(const float* __restrict__ bias) {
    int n = blockIdx.x;
    int t = threadIdx.x;  // col 0..127
    int beg = g_rowptr[n];
    int end = g_rowptr[n + 1];
    float dv = g_dinv[n];
    float acc = dv * dv * g_hw[(size_t)n * HIDDEN + t];
    int j = beg;
    for (; j + 4 <= end; j += 4) {
        int s0 = g_csr_src[j + 0], s1 = g_csr_src[j + 1];
        int s2 = g_csr_src[j + 2], s3 = g_csr_src[j + 3];
        float w0 = g_csr_w[j + 0], w1 = g_csr_w[j + 1];
        float w2 = g_csr_w[j + 2], w3 = g_csr_w[j + 3];
        float v0 = g_hw[(size_t)s0 * HIDDEN + t];
        float v1 = g_hw[(size_t)s1 * HIDDEN + t];
        float v2 = g_hw[(size_t)s2 * HIDDEN + t];
        float v3 = g_hw[(size_t)s3 * HIDDEN + t];
        acc += w0 * v0;
        acc += w1 * v1;
        acc += w2 * v2;
        acc += w3 * v3;
    }
    for (; j < end; j++)
        acc += g_csr_w[j] * g_hw[(size_t)g_csr_src[j] * HIDDEN + t];
    g_h[(size_t)n * HIDDEN + t] = fmaxf(acc + bias[t], 0.f);
}

// ---- pooling: run-length accumulate over sorted batch ids ----
#define NODES_PER_BLOCK 32
__global__ void k_pool(const int* __restrict__ batch) {
    int n0 = blockIdx.x * NODES_PER_BLOCK;
    if (n0 >= N_NODES) return;
    int t = threadIdx.x;  // 0..127 col
    int cur = batch[n0];
    float acc = 0.f;
    int run = 0;
    for (int r = 0; r < NODES_PER_BLOCK; r++) {
        int n = n0 + r;
        if (n >= N_NODES) break;
        int bg = batch[n];
        if (bg != cur) {
            atomicAdd(&g_pool[cur * HIDDEN + t], acc);
            if (t == 0) atomicAdd(&g_cnt[cur], (float)run);
            acc = 0.f; run = 0; cur = bg;
        }
        acc += g_h[(size_t)n * HIDDEN + t];
        run++;
    }
    atomicAdd(&g_pool[cur * HIDDEN + t], acc);
    if (t == 0) atomicAdd(&g_cnt[cur], (float)run);
}

// ---- mean + linear head, write outputs ----
__global__ void k_final(const float* __restrict__ linW, const float* __restrict__ linb,
                        float* __restrict__ out, int emb_off,
                        int write_emb, int write_logits) {
    int g = blockIdx.x;
    int t = threadIdx.x;  // 128
    float c = fmaxf(g_cnt[g], 1.f);
    float e = g_pool[g * HIDDEN + t] / c;
    __shared__ float se[HIDDEN];
    se[t] = e;
    if (write_emb) out[emb_off + g * HIDDEN + t] = e;
    __syncthreads();
    if (write_logits && t < NUM_CLASSES) {
        float acc = linb[t];
#pragma unroll 16
        for (int k = 0; k < HIDDEN; k++)
            acc += se[k] * linW[k * NUM_CLASSES + t];
        out[g * NUM_CLASSES + t] = acc;
    }
}

extern "C" void kernel_launch(void* const* d_in, const int* in_sizes, int n_in,
                              void* d_out, int out_size) {
    const float* x     = (const float*)d_in[0];
    const int*   ei    = (const int*)d_in[1];   // [2, E] (JAX x64 off -> int32)
    const int*   batch = (const int*)d_in[2];
    const float* W0 = (const float*)d_in[3];
    const float* b0 = (const float*)d_in[4];
    const float* W1 = (const float*)d_in[5];
    const float* b1 = (const float*)d_in[6];
    const float* W2 = (const float*)d_in[7];
    const float* b2 = (const float*)d_in[8];
    const float* linW = (const float*)d_in[9];
    const float* linb = (const float*)d_in[10];
    float* out = (float*)d_out;

    const int* src = ei;            // edge_index[0]
    const int* dst = ei + N_EDGES;  // edge_index[1]

    // ---- CSR build (once per launch; edges are layer-invariant) ----
    k_zero<<<(N_NODES + 255) / 256, 256>>>();
    k_deg<<<(N_EDGES + 255) / 256, 256>>>(dst);
    k_dinv<<<(N_NODES + 255) / 256, 256>>>();
    k_scan<<<1, 1024>>>();
    k_fill<<<(N_EDGES + 255) / 256, 256>>>(src, dst);

    const float* Ws[3] = {W0, W1, W2};
    const float* bs[3] = {b0, b1, b2};
    const int gemm_grid = N_NODES / GEMM_ROWS;   // 3125 exact

    for (int l = 0; l < 3; l++) {
        const float* A = (l == 0) ? x : nullptr;  // nullptr -> g_h inside
        k_gemm<<<gemm_grid, HIDDEN>>>(A, Ws[l]);
        k_agg<<<N_NODES, HIDDEN>>>(bs[l]);
    }

    k_pool<<<(N_NODES + NODES_PER_BLOCK - 1) / NODES_PER_BLOCK, HIDDEN>>>(batch);

    // Output: reference returns (logits[64,6], embedding[64,128]) -> 8576 floats.
    int write_logits = 1, write_emb = 0, emb_off = 0;
    if (out_size >= NUM_GRAPHS * (NUM_CLASSES + HIDDEN)) {
        write_emb = 1; emb_off = NUM_GRAPHS * NUM_CLASSES;
    } else if (out_size == NUM_GRAPHS * HIDDEN) {
        write_emb = 1; write_logits = 0; emb_off = 0;
    }
    k_final<<<NUM_GRAPHS, HIDDEN>>>(linW, linb, out, emb_off, write_emb, write_logits);
}

// round 6
// speedup vs baseline: 2.3731x; 1.0672x over previous
#include <cuda_runtime.h>
#include <cuda_bf16.h>

#define N_NODES 50000
#define N_EDGES 800000
#define HIDDEN 128
#define NUM_GRAPHS 64
#define NUM_CLASSES 6

#define SCAN_BLK 256
#define SCAN_NBLK ((N_NODES + SCAN_BLK - 1) / SCAN_BLK)   // 196

// ---- scratch (static device globals; no runtime allocation) ----
__device__ float g_hw[N_NODES * HIDDEN];     // h @ W
__device__ float g_h[N_NODES * HIDDEN];      // layer activation
__device__ float g_dinv[N_NODES];
__device__ int   g_deg[N_NODES];
__device__ int   g_rowptr[N_NODES + 1];
__device__ int   g_cursor[N_NODES];
__device__ int   g_csr_src[N_EDGES];
__device__ float g_csr_w[N_EDGES];
__device__ int   g_bsum[SCAN_NBLK];
__device__ int   g_boff[SCAN_NBLK];
__device__ float g_pool[NUM_GRAPHS * HIDDEN];
__device__ float g_cnt[NUM_GRAPHS];

// ---- init ----
__global__ void k_zero() {
    int i = blockIdx.x * blockDim.x + threadIdx.x;
    if (i < N_NODES) g_deg[i] = 0;
    if (i < NUM_GRAPHS * HIDDEN) g_pool[i] = 0.f;
    if (i < NUM_GRAPHS) g_cnt[i] = 0.f;
}

__global__ void k_deg(const int* __restrict__ dst) {
    int e = blockIdx.x * blockDim.x + threadIdx.x;
    if (e < N_EDGES) atomicAdd(&g_deg[dst[e]], 1);
}

// ---- multi-block exclusive scan of g_deg ----
// pass 1: per-block sums
__global__ void k_scan1() {
    __shared__ int wsum[SCAN_BLK / 32];
    int i = blockIdx.x * SCAN_BLK + threadIdx.x;
    int v = (i < N_NODES) ? g_deg[i] : 0;
#pragma unroll
    for (int o = 16; o > 0; o >>= 1) v += __shfl_down_sync(0xffffffffu, v, o);
    if ((threadIdx.x & 31) == 0) wsum[threadIdx.x >> 5] = v;
    __syncthreads();
    if (threadIdx.x < SCAN_BLK / 32) {
        int s = wsum[threadIdx.x];
#pragma unroll
        for (int o = SCAN_BLK / 64; o > 0; o >>= 1)
            s += __shfl_down_sync(0xffffffffu, s, o);
        if (threadIdx.x == 0) g_bsum[blockIdx.x] = s;
    }
}

// pass 2: single-block exclusive scan of block sums (196 values)
__global__ void k_scan2() {
    __shared__ int wpre[8];
    int lane = threadIdx.x & 31;
    int wid = threadIdx.x >> 5;
    int v = (threadIdx.x < SCAN_NBLK) ? g_bsum[threadIdx.x] : 0;
    int x = v;
#pragma unroll
    for (int o = 1; o < 32; o <<= 1) {
        int y = __shfl_up_sync(0xffffffffu, x, o);
        if (lane >= o) x += y;
    }
    if (lane == 31) wpre[wid] = x;
    __syncthreads();
    if (wid == 0 && lane < 8) {
        int s = wpre[lane];
#pragma unroll
        for (int o = 1; o < 8; o <<= 1) {
            int y = __shfl_up_sync(0xffu, s, o);
            if (lane >= o) s += y;
        }
        wpre[lane] = s;
    }
    __syncthreads();
    int excl = (x - v) + (wid > 0 ? wpre[wid - 1] : 0);
    if (threadIdx.x < SCAN_NBLK) g_boff[threadIdx.x] = excl;
}

// pass 3: per-block scan + apply offset; also dinv + cursor init
__global__ void k_scan3() {
    __shared__ int wpre[SCAN_BLK / 32];
    int lane = threadIdx.x & 31;
    int wid = threadIdx.x >> 5;
    int i = blockIdx.x * SCAN_BLK + threadIdx.x;
    int v = (i < N_NODES) ? g_deg[i] : 0;
    int x = v;
#pragma unroll
    for (int o = 1; o < 32; o <<= 1) {
        int y = __shfl_up_sync(0xffffffffu, x, o);
        if (lane >= o) x += y;
    }
    if (lane == 31) wpre[wid] = x;
    __syncthreads();
    if (wid == 0 && lane < SCAN_BLK / 32) {
        int s = wpre[lane];
#pragma unroll
        for (int o = 1; o < SCAN_BLK / 32; o <<= 1) {
            int y = __shfl_up_sync((1u << (SCAN_BLK / 32)) - 1u, s, o);
            if (lane >= o) s += y;
        }
        wpre[lane] = s;
    }
    __syncthreads();
    if (i < N_NODES) {
        int excl = (x - v) + (wid > 0 ? wpre[wid - 1] : 0) + g_boff[blockIdx.x];
        g_rowptr[i] = excl;
        g_cursor[i] = excl;
        g_dinv[i] = rsqrtf((float)(v + 1));   // +1 self-loop
        if (i == 0) g_rowptr[N_NODES] = N_EDGES;
    }
}

// ---- fill CSR (src index + edge weight), bucketed by dst ----
__global__ void k_fill(const int* __restrict__ src, const int* __restrict__ dst) {
    int e = blockIdx.x * blockDim.x + threadIdx.x;
    if (e >= N_EDGES) return;
    int s = src[e];
    int d = dst[e];
    int pos = atomicAdd(&g_cursor[d], 1);
    g_csr_src[pos] = s;
    g_csr_w[pos] = g_dinv[s] * g_dinv[d];
}

// ---- dense projection: hw = A @ W  (A [N,128] row-major, W [128,128]) ----
#define GEMM_ROWS 16
__global__ void k_gemm(const float* __restrict__ A, const float* __restrict__ W) {
    if (A == nullptr) A = g_h;   // layers 1,2 read previous activation
    __shared__ float4 shA[GEMM_ROWS][HIDDEN / 4];   // 8 KB
    int row0 = blockIdx.x * GEMM_ROWS;
    int t = threadIdx.x;  // 0..127, output column
    const float4* Af = (const float4*)(A + (size_t)row0 * HIDDEN);
    float4* shf = &shA[0][0];
#pragma unroll
    for (int i = 0; i < 4; i++)
        shf[i * 128 + t] = Af[i * 128 + t];
    __syncthreads();
    float acc[GEMM_ROWS];
#pragma unroll
    for (int r = 0; r < GEMM_ROWS; r++) acc[r] = 0.f;
#pragma unroll 4
    for (int k4 = 0; k4 < HIDDEN / 4; k4++) {
        float w0 = __ldg(&W[(k4 * 4 + 0) * HIDDEN + t]);
        float w1 = __ldg(&W[(k4 * 4 + 1) * HIDDEN + t]);
        float w2 = __ldg(&W[(k4 * 4 + 2) * HIDDEN + t]);
        float w3 = __ldg(&W[(k4 * 4 + 3) * HIDDEN + t]);
#pragma unroll
        for (int r = 0; r < GEMM_ROWS; r++) {
            float4 a = shA[r][k4];
            acc[r] += a.x * w0 + a.y * w1 + a.z * w2 + a.w * w3;
        }
    }
#pragma unroll
    for (int r = 0; r < GEMM_ROWS; r++)
        g_hw[(size_t)(row0 + r) * HIDDEN + t] = acc[r];
}

// ---- fused aggregate (CSR gather) + self-loop + bias + ReLU ----
__global__ void k_agg(const float* __restrict__ bias) {
    int n = blockIdx.x;
    int t = threadIdx.x;  // col 0..127
    int beg = g_rowptr[n];
    int end = g_rowptr[n + 1];
    float dv = g_dinv[n];
    float acc = dv * dv * g_hw[(size_t)n * HIDDEN + t];
    int j = beg;
    for (; j + 4 <= end; j += 4) {
        int s0 = g_csr_src[j + 0], s1 = g_csr_src[j + 1];
        int s2 = g_csr_src[j + 2], s3 = g_csr_src[j + 3];
        float w0 = g_csr_w[j + 0], w1 = g_csr_w[j + 1];
        float w2 = g_csr_w[j + 2], w3 = g_csr_w[j + 3];
        float v0 = g_hw[(size_t)s0 * HIDDEN + t];
        float v1 = g_hw[(size_t)s1 * HIDDEN + t];
        float v2 = g_hw[(size_t)s2 * HIDDEN + t];
        float v3 = g_hw[(size_t)s3 * HIDDEN + t];
        acc += w0 * v0;
        acc += w1 * v1;
        acc += w2 * v2;
        acc += w3 * v3;
    }
    for (; j < end; j++)
        acc += g_csr_w[j] * g_hw[(size_t)g_csr_src[j] * HIDDEN + t];
    g_h[(size_t)n * HIDDEN + t] = fmaxf(acc + bias[t], 0.f);
}

// ---- pooling: run-length accumulate over sorted batch ids ----
#define NODES_PER_BLOCK 32
__global__ void k_pool(const int* __restrict__ batch) {
    int n0 = blockIdx.x * NODES_PER_BLOCK;
    if (n0 >= N_NODES) return;
    int t = threadIdx.x;  // 0..127 col
    int cur = batch[n0];
    float acc = 0.f;
    int run = 0;
    for (int r = 0; r < NODES_PER_BLOCK; r++) {
        int n = n0 + r;
        if (n >= N_NODES) break;
        int bg = batch[n];
        if (bg != cur) {
            atomicAdd(&g_pool[cur * HIDDEN + t], acc);
            if (t == 0) atomicAdd(&g_cnt[cur], (float)run);
            acc = 0.f; run = 0; cur = bg;
        }
        acc += g_h[(size_t)n * HIDDEN + t];
        run++;
    }
    atomicAdd(&g_pool[cur * HIDDEN + t], acc);
    if (t == 0) atomicAdd(&g_cnt[cur], (float)run);
}

// ---- mean + linear head, write outputs ----
__global__ void k_final(const float* __restrict__ linW, const float* __restrict__ linb,
                        float* __restrict__ out, int emb_off,
                        int write_emb, int write_logits) {
    int g = blockIdx.x;
    int t = threadIdx.x;  // 128
    float c = fmaxf(g_cnt[g], 1.f);
    float e = g_pool[g * HIDDEN + t] / c;
    __shared__ float se[HIDDEN];
    se[t] = e;
    if (write_emb) out[emb_off + g * HIDDEN + t] = e;
    __syncthreads();
    if (write_logits && t < NUM_CLASSES) {
        float acc = linb[t];
#pragma unroll 16
        for (int k = 0; k < HIDDEN; k++)
            acc += se[k] * linW[k * NUM_CLASSES + t];
        out[g * NUM_CLASSES + t] = acc;
    }
}

extern "C" void kernel_launch(void* const* d_in, const int* in_sizes, int n_in,
                              void* d_out, int out_size) {
    const float* x     = (const float*)d_in[0];
    const int*   ei    = (const int*)d_in[1];   // [2, E] (JAX x64 off -> int32)
    const int*   batch = (const int*)d_in[2];
    const float* W0 = (const float*)d_in[3];
    const float* b0 = (const float*)d_in[4];
    const float* W1 = (const float*)d_in[5];
    const float* b1 = (const float*)d_in[6];
    const float* W2 = (const float*)d_in[7];
    const float* b2 = (const float*)d_in[8];
    const float* linW = (const float*)d_in[9];
    const float* linb = (const float*)d_in[10];
    float* out = (float*)d_out;

    const int* src = ei;            // edge_index[0]
    const int* dst = ei + N_EDGES;  // edge_index[1]

    // ---- CSR build (once per launch; edges are layer-invariant) ----
    k_zero<<<(N_NODES + 255) / 256, 256>>>();
    k_deg<<<(N_EDGES + 255) / 256, 256>>>(dst);
    k_scan1<<<SCAN_NBLK, SCAN_BLK>>>();
    k_scan2<<<1, SCAN_BLK>>>();
    k_scan3<<<SCAN_NBLK, SCAN_BLK>>>();
    k_fill<<<(N_EDGES + 255) / 256, 256>>>(src, dst);

    const float* Ws[3] = {W0, W1, W2};
    const float* bs[3] = {b0, b1, b2};
    const int gemm_grid = N_NODES / GEMM_ROWS;   // 3125 exact

    for (int l = 0; l < 3; l++) {
        const float* A = (l == 0) ? x : nullptr;  // nullptr -> g_h inside
        k_gemm<<<gemm_grid, HIDDEN>>>(A, Ws[l]);
        k_agg<<<N_NODES, HIDDEN>>>(bs[l]);
    }

    k_pool<<<(N_NODES + NODES_PER_BLOCK - 1) / NODES_PER_BLOCK, HIDDEN>>>(batch);

    // Output: reference returns (logits[64,6], embedding[64,128]) -> 8576 floats.
    int write_logits = 1, write_emb = 0, emb_off = 0;
    if (out_size >= NUM_GRAPHS * (NUM_CLASSES + HIDDEN)) {
        write_emb = 1; emb_off = NUM_GRAPHS * NUM_CLASSES;
    } else if (out_size == NUM_GRAPHS * HIDDEN) {
        write_emb = 1; write_logits = 0; emb_off = 0;
    }
    k_final<<<NUM_GRAPHS, HIDDEN>>>(linW, linb, out, emb_off, write_emb, write_logits);
}

// round 8
// speedup vs baseline: 2.9256x; 1.2328x over previous
#include <cuda_runtime.h>
#include <cuda_fp16.h>

#define N_NODES 50000
#define N_EDGES 800000
#define HIDDEN 128
#define NUM_GRAPHS 64
#define NUM_CLASSES 6

#define SCAN_BLK 256
#define SCAN_NBLK ((N_NODES + SCAN_BLK - 1) / SCAN_BLK)   // 196

// ---- scratch (static device globals; no runtime allocation) ----
__device__ __half2 g_hw2[N_NODES * (HIDDEN / 2)];   // h @ W, fp16 packed
__device__ float   g_h[N_NODES * HIDDEN];           // layer activation (fp32)
__device__ float   g_dinv[N_NODES];
__device__ int     g_deg[N_NODES];
__device__ int     g_rowptr[N_NODES + 1];
__device__ int     g_cursor[N_NODES];
__device__ int     g_csr_src[N_EDGES];
__device__ float   g_csr_w[N_EDGES];
__device__ int     g_bsum[SCAN_NBLK];
__device__ int     g_boff[SCAN_NBLK];
__device__ float   g_pool[NUM_GRAPHS * HIDDEN];
__device__ float   g_cnt[NUM_GRAPHS];

// ---- init ----
__global__ void k_zero() {
    int i = blockIdx.x * blockDim.x + threadIdx.x;
    if (i < N_NODES) g_deg[i] = 0;
    if (i < NUM_GRAPHS * HIDDEN) g_pool[i] = 0.f;
    if (i < NUM_GRAPHS) g_cnt[i] = 0.f;
}

__global__ void k_deg(const int* __restrict__ dst) {
    int e = blockIdx.x * blockDim.x + threadIdx.x;
    if (e < N_EDGES) atomicAdd(&g_deg[dst[e]], 1);
}

// ---- multi-block exclusive scan of g_deg ----
__global__ void k_scan1() {
    __shared__ int wsum[SCAN_BLK / 32];
    int i = blockIdx.x * SCAN_BLK + threadIdx.x;
    int v = (i < N_NODES) ? g_deg[i] : 0;
#pragma unroll
    for (int o = 16; o > 0; o >>= 1) v += __shfl_down_sync(0xffffffffu, v, o);
    if ((threadIdx.x & 31) == 0) wsum[threadIdx.x >> 5] = v;
    __syncthreads();
    if (threadIdx.x < SCAN_BLK / 32) {
        int s = wsum[threadIdx.x];
#pragma unroll
        for (int o = SCAN_BLK / 64; o > 0; o >>= 1)
            s += __shfl_down_sync(0xffffffffu, s, o);
        if (threadIdx.x == 0) g_bsum[blockIdx.x] = s;
    }
}

__global__ void k_scan2() {
    __shared__ int wpre[8];
    int lane = threadIdx.x & 31;
    int wid = threadIdx.x >> 5;
    int v = (threadIdx.x < SCAN_NBLK) ? g_bsum[threadIdx.x] : 0;
    int x = v;
#pragma unroll
    for (int o = 1; o < 32; o <<= 1) {
        int y = __shfl_up_sync(0xffffffffu, x, o);
        if (lane >= o) x += y;
    }
    if (lane == 31) wpre[wid] = x;
    __syncthreads();
    if (wid == 0 && lane < 8) {
        int s = wpre[lane];
#pragma unroll
        for (int o = 1; o < 8; o <<= 1) {
            int y = __shfl_up_sync(0xffu, s, o);
            if (lane >= o) s += y;
        }
        wpre[lane] = s;
    }
    __syncthreads();
    int excl = (x - v) + (wid > 0 ? wpre[wid - 1] : 0);
    if (threadIdx.x < SCAN_NBLK) g_boff[threadIdx.x] = excl;
}

__global__ void k_scan3() {
    __shared__ int wpre[SCAN_BLK / 32];
    int lane = threadIdx.x & 31;
    int wid = threadIdx.x >> 5;
    int i = blockIdx.x * SCAN_BLK + threadIdx.x;
    int v = (i < N_NODES) ? g_deg[i] : 0;
    int x = v;
#pragma unroll
    for (int o = 1; o < 32; o <<= 1) {
        int y = __shfl_up_sync(0xffffffffu, x, o);
        if (lane >= o) x += y;
    }
    if (lane == 31) wpre[wid] = x;
    __syncthreads();
    if (wid == 0 && lane < SCAN_BLK / 32) {
        int s = wpre[lane];
#pragma unroll
        for (int o = 1; o < SCAN_BLK / 32; o <<= 1) {
            int y = __shfl_up_sync((1u << (SCAN_BLK / 32)) - 1u, s, o);
            if (lane >= o) s += y;
        }
        wpre[lane] = s;
    }
    __syncthreads();
    if (i < N_NODES) {
        int excl = (x - v) + (wid > 0 ? wpre[wid - 1] : 0) + g_boff[blockIdx.x];
        g_rowptr[i] = excl;
        g_cursor[i] = excl;
        g_dinv[i] = rsqrtf((float)(v + 1));   // +1 self-loop
        if (i == 0) g_rowptr[N_NODES] = N_EDGES;
    }
}

// ---- fill CSR (src index + edge weight), bucketed by dst ----
__global__ void k_fill(const int* __restrict__ src, const int* __restrict__ dst) {
    int e = blockIdx.x * blockDim.x + threadIdx.x;
    if (e >= N_EDGES) return;
    int s = src[e];
    int d = dst[e];
    int pos = atomicAdd(&g_cursor[d], 1);
    g_csr_src[pos] = s;
    g_csr_w[pos] = g_dinv[s] * g_dinv[d];
}

// ---- dense projection: hw = A @ W  -> fp16 packed output ----
#define GEMM_ROWS 16
__global__ void k_gemm(const float* __restrict__ A, const float* __restrict__ W) {
    if (A == nullptr) A = g_h;   // layers 1,2 read previous activation
    __shared__ float4 shA[GEMM_ROWS][HIDDEN / 4];   // 8 KB
    int row0 = blockIdx.x * GEMM_ROWS;
    int t = threadIdx.x;  // 0..127, output column
    const float4* Af = (const float4*)(A + (size_t)row0 * HIDDEN);
    float4* shf = &shA[0][0];
#pragma unroll
    for (int i = 0; i < 4; i++)
        shf[i * 128 + t] = Af[i * 128 + t];
    __syncthreads();
    float acc[GEMM_ROWS];
#pragma unroll
    for (int r = 0; r < GEMM_ROWS; r++) acc[r] = 0.f;
#pragma unroll 4
    for (int k4 = 0; k4 < HIDDEN / 4; k4++) {
        float w0 = __ldg(&W[(k4 * 4 + 0) * HIDDEN + t]);
        float w1 = __ldg(&W[(k4 * 4 + 1) * HIDDEN + t]);
        float w2 = __ldg(&W[(k4 * 4 + 2) * HIDDEN + t]);
        float w3 = __ldg(&W[(k4 * 4 + 3) * HIDDEN + t]);
#pragma unroll
        for (int r = 0; r < GEMM_ROWS; r++) {
            float4 a = shA[r][k4];
            acc[r] += a.x * w0 + a.y * w1 + a.z * w2 + a.w * w3;
        }
    }
    // epilogue: pack adjacent columns into half2 via shfl pairing
#pragma unroll
    for (int r = 0; r < GEMM_ROWS; r++) {
        float partner = __shfl_xor_sync(0xffffffffu, acc[r], 1);
        if ((t & 1) == 0) {
            __half2 hv = __floats2half2_rn(acc[r], partner);  // (low=col t, high=col t+1)
            g_hw2[(size_t)(row0 + r) * (HIDDEN / 2) + (t >> 1)] = hv;
        }
    }
}

// ---- fused aggregate (CSR half2 gather) + self-loop + bias + ReLU ----
// 64 threads per node (one half2 lane each), 4 nodes per 256-thread block.
#define AGG_NODES 4
__global__ void k_agg(const float* __restrict__ bias) {
    int n = blockIdx.x * AGG_NODES + (threadIdx.x >> 6);
    int t = threadIdx.x & 63;   // half2 column index (cols 2t, 2t+1)
    int beg = g_rowptr[n];
    int end = g_rowptr[n + 1];
    float dv = g_dinv[n];
    float2 self = __half22float2(g_hw2[(size_t)n * 64 + t]);
    float ax = dv * dv * self.x;
    float ay = dv * dv * self.y;
    int j = beg;
    for (; j + 4 <= end; j += 4) {
        int s0 = g_csr_src[j + 0], s1 = g_csr_src[j + 1];
        int s2 = g_csr_src[j + 2], s3 = g_csr_src[j + 3];
        float w0 = g_csr_w[j + 0], w1 = g_csr_w[j + 1];
        float w2 = g_csr_w[j + 2], w3 = g_csr_w[j + 3];
        float2 v0 = __half22float2(g_hw2[(size_t)s0 * 64 + t]);
        float2 v1 = __half22float2(g_hw2[(size_t)s1 * 64 + t]);
        float2 v2 = __half22float2(g_hw2[(size_t)s2 * 64 + t]);
        float2 v3 = __half22float2(g_hw2[(size_t)s3 * 64 + t]);
        ax += w0 * v0.x; ay += w0 * v0.y;
        ax += w1 * v1.x; ay += w1 * v1.y;
        ax += w2 * v2.x; ay += w2 * v2.y;
        ax += w3 * v3.x; ay += w3 * v3.y;
    }
    for (; j < end; j++) {
        float w = g_csr_w[j];
        float2 v = __half22float2(g_hw2[(size_t)g_csr_src[j] * 64 + t]);
        ax += w * v.x; ay += w * v.y;
    }
    float2 b = ((const float2*)bias)[t];
    float2 r;
    r.x = fmaxf(ax + b.x, 0.f);
    r.y = fmaxf(ay + b.y, 0.f);
    ((float2*)g_h)[(size_t)n * 64 + t] = r;
}

// ---- pooling: run-length accumulate over sorted batch ids ----
#define NODES_PER_BLOCK 32
__global__ void k_pool(const int* __restrict__ batch) {
    int n0 = blockIdx.x * NODES_PER_BLOCK;
    if (n0 >= N_NODES) return;
    int t = threadIdx.x;  // 0..127 col
    int cur = batch[n0];
    float acc = 0.f;
    int run = 0;
    for (int r = 0; r < NODES_PER_BLOCK; r++) {
        int n = n0 + r;
        if (n >= N_NODES) break;
        int bg = batch[n];
        if (bg != cur) {
            atomicAdd(&g_pool[cur * HIDDEN + t], acc);
            if (t == 0) atomicAdd(&g_cnt[cur], (float)run);
            acc = 0.f; run = 0; cur = bg;
        }
        acc += g_h[(size_t)n * HIDDEN + t];
        run++;
    }
    atomicAdd(&g_pool[cur * HIDDEN + t], acc);
    if (t == 0) atomicAdd(&g_cnt[cur], (float)run);
}

// ---- mean + linear head, write outputs ----
__global__ void k_final(const float* __restrict__ linW, const float* __restrict__ linb,
                        float* __restrict__ out, int emb_off,
                        int write_emb, int write_logits) {
    int g = blockIdx.x;
    int t = threadIdx.x;  // 128
    float c = fmaxf(g_cnt[g], 1.f);
    float e = g_pool[g * HIDDEN + t] / c;
    __shared__ float se[HIDDEN];
    se[t] = e;
    if (write_emb) out[emb_off + g * HIDDEN + t] = e;
    __syncthreads();
    if (write_logits && t < NUM_CLASSES) {
        float acc = linb[t];
#pragma unroll 16
        for (int k = 0; k < HIDDEN; k++)
            acc += se[k] * linW[k * NUM_CLASSES + t];
        out[g * NUM_CLASSES + t] = acc;
    }
}

extern "C" void kernel_launch(void* const* d_in, const int* in_sizes, int n_in,
                              void* d_out, int out_size) {
    const float* x     = (const float*)d_in[0];
    const int*   ei    = (const int*)d_in[1];   // [2, E] (JAX x64 off -> int32)
    const int*   batch = (const int*)d_in[2];
    const float* W0 = (const float*)d_in[3];
    const float* b0 = (const float*)d_in[4];
    const float* W1 = (const float*)d_in[5];
    const float* b1 = (const float*)d_in[6];
    const float* W2 = (const float*)d_in[7];
    const float* b2 = (const float*)d_in[8];
    const float* linW = (const float*)d_in[9];
    const float* linb = (const float*)d_in[10];
    float* out = (float*)d_out;

    const int* src = ei;            // edge_index[0]
    const int* dst = ei + N_EDGES;  // edge_index[1]

    // ---- CSR build (once per launch; edges are layer-invariant) ----
    k_zero<<<(N_NODES + 255) / 256, 256>>>();
    k_deg<<<(N_EDGES + 255) / 256, 256>>>(dst);
    k_scan1<<<SCAN_NBLK, SCAN_BLK>>>();
    k_scan2<<<1, SCAN_BLK>>>();
    k_scan3<<<SCAN_NBLK, SCAN_BLK>>>();
    k_fill<<<(N_EDGES + 255) / 256, 256>>>(src, dst);

    const float* Ws[3] = {W0, W1, W2};
    const float* bs[3] = {b0, b1, b2};
    const int gemm_grid = N_NODES / GEMM_ROWS;   // 3125 exact
    const int agg_grid = N_NODES / AGG_NODES;    // 12500 exact

    for (int l = 0; l < 3; l++) {
        const float* A = (l == 0) ? x : nullptr;  // nullptr -> g_h inside
        k_gemm<<<gemm_grid, HIDDEN>>>(A, Ws[l]);
        k_agg<<<agg_grid, 256>>>(bs[l]);
    }

    k_pool<<<(N_NODES + NODES_PER_BLOCK - 1) / NODES_PER_BLOCK, HIDDEN>>>(batch);

    // Output: reference returns (logits[64,6], embedding[64,128]) -> 8576 floats.
    int write_logits = 1, write_emb = 0, emb_off = 0;
    if (out_size >= NUM_GRAPHS * (NUM_CLASSES + HIDDEN)) {
        write_emb = 1; emb_off = NUM_GRAPHS * NUM_CLASSES;
    } else if (out_size == NUM_GRAPHS * HIDDEN) {
        write_emb = 1; write_logits = 0; emb_off = 0;
    }
    k_final<<<NUM_GRAPHS, HIDDEN>>>(linW, linb, out, emb_off, write_emb, write_logits);
}

// round 9
// speedup vs baseline: 3.2796x; 1.1210x over previous
#include <cuda_runtime.h>
#include <cuda_fp16.h>
#include <mma.h>

using namespace nvcuda;

#define N_NODES 50000
#define N_EDGES 800000
#define HIDDEN 128
#define NUM_GRAPHS 64
#define NUM_CLASSES 6

#define SCAN_BLK 256
#define SCAN_NBLK ((N_NODES + SCAN_BLK - 1) / SCAN_BLK)   // 196

// ---- scratch (static device globals; no runtime allocation) ----
__device__ __half2 g_hw2[N_NODES * (HIDDEN / 2)];   // h @ W, fp16 packed
__device__ __half2 g_h2[N_NODES * (HIDDEN / 2)];    // layer activation, fp16 packed
__device__ __half  g_Wh[3 * HIDDEN * HIDDEN];       // fp16 weights
__device__ float   g_dinv[N_NODES];
__device__ int     g_deg[N_NODES];
__device__ int     g_rowptr[N_NODES + 1];
__device__ int     g_cursor[N_NODES];
__device__ int     g_csr_src[N_EDGES];
__device__ float   g_csr_w[N_EDGES];
__device__ int     g_bsum[SCAN_NBLK];
__device__ int     g_boff[SCAN_NBLK];
__device__ float   g_pool[NUM_GRAPHS * HIDDEN];
__device__ float   g_cnt[NUM_GRAPHS];

// ---- input conversions (once per launch) ----
__global__ void k_cvt_x(const float* __restrict__ x) {
    int i = blockIdx.x * blockDim.x + threadIdx.x;   // over N*64 half2 slots
    if (i < N_NODES * (HIDDEN / 2)) {
        float2 v = ((const float2*)x)[i];
        g_h2[i] = __floats2half2_rn(v.x, v.y);
    }
}

__global__ void k_cvt_w(const float* __restrict__ W0, const float* __restrict__ W1,
                        const float* __restrict__ W2) {
    int i = blockIdx.x * blockDim.x + threadIdx.x;
    if (i < HIDDEN * HIDDEN) {
        g_Wh[i] = __float2half(W0[i]);
        g_Wh[HIDDEN * HIDDEN + i] = __float2half(W1[i]);
        g_Wh[2 * HIDDEN * HIDDEN + i] = __float2half(W2[i]);
    }
}

// ---- init ----
__global__ void k_zero() {
    int i = blockIdx.x * blockDim.x + threadIdx.x;
    if (i < N_NODES) g_deg[i] = 0;
    if (i < NUM_GRAPHS * HIDDEN) g_pool[i] = 0.f;
    if (i < NUM_GRAPHS) g_cnt[i] = 0.f;
}

__global__ void k_deg(const int* __restrict__ dst) {
    int e = blockIdx.x * blockDim.x + threadIdx.x;
    if (e < N_EDGES) atomicAdd(&g_deg[dst[e]], 1);
}

// ---- multi-block exclusive scan of g_deg ----
__global__ void k_scan1() {
    __shared__ int wsum[SCAN_BLK / 32];
    int i = blockIdx.x * SCAN_BLK + threadIdx.x;
    int v = (i < N_NODES) ? g_deg[i] : 0;
#pragma unroll
    for (int o = 16; o > 0; o >>= 1) v += __shfl_down_sync(0xffffffffu, v, o);
    if ((threadIdx.x & 31) == 0) wsum[threadIdx.x >> 5] = v;
    __syncthreads();
    if (threadIdx.x < SCAN_BLK / 32) {
        int s = wsum[threadIdx.x];
#pragma unroll
        for (int o = SCAN_BLK / 64; o > 0; o >>= 1)
            s += __shfl_down_sync(0xffffffffu, s, o);
        if (threadIdx.x == 0) g_bsum[blockIdx.x] = s;
    }
}

__global__ void k_scan2() {
    __shared__ int wpre[8];
    int lane = threadIdx.x & 31;
    int wid = threadIdx.x >> 5;
    int v = (threadIdx.x < SCAN_NBLK) ? g_bsum[threadIdx.x] : 0;
    int x = v;
#pragma unroll
    for (int o = 1; o < 32; o <<= 1) {
        int y = __shfl_up_sync(0xffffffffu, x, o);
        if (lane >= o) x += y;
    }
    if (lane == 31) wpre[wid] = x;
    __syncthreads();
    if (wid == 0 && lane < 8) {
        int s = wpre[lane];
#pragma unroll
        for (int o = 1; o < 8; o <<= 1) {
            int y = __shfl_up_sync(0xffu, s, o);
            if (lane >= o) s += y;
        }
        wpre[lane] = s;
    }
    __syncthreads();
    int excl = (x - v) + (wid > 0 ? wpre[wid - 1] : 0);
    if (threadIdx.x < SCAN_NBLK) g_boff[threadIdx.x] = excl;
}

__global__ void k_scan3() {
    __shared__ int wpre[SCAN_BLK / 32];
    int lane = threadIdx.x & 31;
    int wid = threadIdx.x >> 5;
    int i = blockIdx.x * SCAN_BLK + threadIdx.x;
    int v = (i < N_NODES) ? g_deg[i] : 0;
    int x = v;
#pragma unroll
    for (int o = 1; o < 32; o <<= 1) {
        int y = __shfl_up_sync(0xffffffffu, x, o);
        if (lane >= o) x += y;
    }
    if (lane == 31) wpre[wid] = x;
    __syncthreads();
    if (wid == 0 && lane < SCAN_BLK / 32) {
        int s = wpre[lane];
#pragma unroll
        for (int o = 1; o < SCAN_BLK / 32; o <<= 1) {
            int y = __shfl_up_sync((1u << (SCAN_BLK / 32)) - 1u, s, o);
            if (lane >= o) s += y;
        }
        wpre[lane] = s;
    }
    __syncthreads();
    if (i < N_NODES) {
        int excl = (x - v) + (wid > 0 ? wpre[wid - 1] : 0) + g_boff[blockIdx.x];
        g_rowptr[i] = excl;
        g_cursor[i] = excl;
        g_dinv[i] = rsqrtf((float)(v + 1));   // +1 self-loop
        if (i == 0) g_rowptr[N_NODES] = N_EDGES;
    }
}

// ---- fill CSR (src index + edge weight), bucketed by dst ----
__global__ void k_fill(const int* __restrict__ src, const int* __restrict__ dst) {
    int e = blockIdx.x * blockDim.x + threadIdx.x;
    if (e >= N_EDGES) return;
    int s = src[e];
    int d = dst[e];
    int pos = atomicAdd(&g_cursor[d], 1);
    g_csr_src[pos] = s;
    g_csr_w[pos] = g_dinv[s] * g_dinv[d];
}

// ---- tensor-core projection: hw = h @ W (fp16 in, fp32 accum, fp16 out) ----
// Block: 256 threads (8 warps) handles 64 rows x 128 cols.
// Warp w: row-tile = w>>1 (16 rows), col-half = w&1 (64 cols = 4 frags).
#define TC_ROWS 64
__global__ void __launch_bounds__(256) k_gemm_tc(int layer) {
    __shared__ __align__(256) char smem_raw[TC_ROWS * HIDDEN * 4];  // 32 KB
    __half* sB = (__half*)smem_raw;       // phase 1: B tile 128x128 fp16
    float*  sC = (float*)smem_raw;        // phase 2: C staging 64x128 fp32
    int tid = threadIdx.x;

    // load B (128x128 fp16 = 32 KB) coalesced
    const int4* Bv = (const int4*)(g_Wh + (size_t)layer * HIDDEN * HIDDEN);
    int4* sBv = (int4*)sB;
#pragma unroll
    for (int i = 0; i < 8; i++)
        sBv[tid + i * 256] = Bv[tid + i * 256];
    __syncthreads();

    int warp = tid >> 5;
    int rt = warp >> 1;       // 0..3
    int ch = warp & 1;        // 0..1
    int row0 = blockIdx.x * TC_ROWS + rt * 16;
    bool active = row0 < N_NODES;   // warp-uniform

    wmma::fragment<wmma::accumulator, 16, 16, 16, float> c[4];
#pragma unroll
    for (int j = 0; j < 4; j++) wmma::fill_fragment(c[j], 0.f);

    if (active) {
        const __half* A = (const __half*)g_h2;
#pragma unroll
        for (int k = 0; k < 8; k++) {
            wmma::fragment<wmma::matrix_a, 16, 16, 16, __half, wmma::row_major> a;
            wmma::load_matrix_sync(a, A + (size_t)row0 * HIDDEN + k * 16, HIDDEN);
#pragma unroll
            for (int j = 0; j < 4; j++) {
                wmma::fragment<wmma::matrix_b, 16, 16, 16, __half, wmma::row_major> b;
                wmma::load_matrix_sync(b, sB + (k * 16) * HIDDEN + ch * 64 + j * 16, HIDDEN);
                wmma::mma_sync(c[j], a, b, c[j]);
            }
        }
    }
    __syncthreads();   // everyone done with sB
    if (active) {
#pragma unroll
        for (int j = 0; j < 4; j++)
            wmma::store_matrix_sync(sC + (rt * 16) * HIDDEN + ch * 64 + j * 16,
                                    c[j], HIDDEN, wmma::mem_row_major);
    }
    __syncthreads();

    // convert fp32 staging -> half2 global (coalesced)
    int row_base = blockIdx.x * TC_ROWS;
#pragma unroll
    for (int i = 0; i < 16; i++) {
        int idx = tid + i * 256;          // half2 slot in tile: 0..4095
        int r = idx >> 6;
        if (row_base + r < N_NODES) {
            float2 v = ((float2*)sC)[idx];
            g_hw2[(size_t)(row_base + r) * 64 + (idx & 63)] = __floats2half2_rn(v.x, v.y);
        }
    }
}

// ---- fused aggregate (CSR half2 gather) + self-loop + bias + ReLU -> fp16 h ----
#define AGG_NODES 4
__global__ void k_agg(const float* __restrict__ bias) {
    int n = blockIdx.x * AGG_NODES + (threadIdx.x >> 6);
    int t = threadIdx.x & 63;   // half2 column index (cols 2t, 2t+1)
    int beg = g_rowptr[n];
    int end = g_rowptr[n + 1];
    float dv = g_dinv[n];
    float2 self = __half22float2(g_hw2[(size_t)n * 64 + t]);
    float ax = dv * dv * self.x;
    float ay = dv * dv * self.y;
    int j = beg;
    for (; j + 4 <= end; j += 4) {
        int s0 = g_csr_src[j + 0], s1 = g_csr_src[j + 1];
        int s2 = g_csr_src[j + 2], s3 = g_csr_src[j + 3];
        float w0 = g_csr_w[j + 0], w1 = g_csr_w[j + 1];
        float w2 = g_csr_w[j + 2], w3 = g_csr_w[j + 3];
        float2 v0 = __half22float2(g_hw2[(size_t)s0 * 64 + t]);
        float2 v1 = __half22float2(g_hw2[(size_t)s1 * 64 + t]);
        float2 v2 = __half22float2(g_hw2[(size_t)s2 * 64 + t]);
        float2 v3 = __half22float2(g_hw2[(size_t)s3 * 64 + t]);
        ax += w0 * v0.x; ay += w0 * v0.y;
        ax += w1 * v1.x; ay += w1 * v1.y;
        ax += w2 * v2.x; ay += w2 * v2.y;
        ax += w3 * v3.x; ay += w3 * v3.y;
    }
    for (; j < end; j++) {
        float w = g_csr_w[j];
        float2 v = __half22float2(g_hw2[(size_t)g_csr_src[j] * 64 + t]);
        ax += w * v.x; ay += w * v.y;
    }
    float2 b = ((const float2*)bias)[t];
    g_h2[(size_t)n * 64 + t] =
        __floats2half2_rn(fmaxf(ax + b.x, 0.f), fmaxf(ay + b.y, 0.f));
}

// ---- pooling: run-length accumulate over sorted batch ids (fp16 h, fp32 acc) ----
#define NODES_PER_BLOCK 32
__global__ void k_pool(const int* __restrict__ batch) {
    int n0 = blockIdx.x * NODES_PER_BLOCK;
    if (n0 >= N_NODES) return;
    int t = threadIdx.x;  // 0..63, half2 column pair
    int cur = batch[n0];
    float ax = 0.f, ay = 0.f;
    int run = 0;
    for (int r = 0; r < NODES_PER_BLOCK; r++) {
        int n = n0 + r;
        if (n >= N_NODES) break;
        int bg = batch[n];
        if (bg != cur) {
            atomicAdd(&g_pool[cur * HIDDEN + 2 * t], ax);
            atomicAdd(&g_pool[cur * HIDDEN + 2 * t + 1], ay);
            if (t == 0) atomicAdd(&g_cnt[cur], (float)run);
            ax = 0.f; ay = 0.f; run = 0; cur = bg;
        }
        float2 v = __half22float2(g_h2[(size_t)n * 64 + t]);
        ax += v.x; ay += v.y;
        run++;
    }
    atomicAdd(&g_pool[cur * HIDDEN + 2 * t], ax);
    atomicAdd(&g_pool[cur * HIDDEN + 2 * t + 1], ay);
    if (t == 0) atomicAdd(&g_cnt[cur], (float)run);
}

// ---- mean + linear head, write outputs ----
__global__ void k_final(const float* __restrict__ linW, const float* __restrict__ linb,
                        float* __restrict__ out, int emb_off,
                        int write_emb, int write_logits) {
    int g = blockIdx.x;
    int t = threadIdx.x;  // 128
    float c = fmaxf(g_cnt[g], 1.f);
    float e = g_pool[g * HIDDEN + t] / c;
    __shared__ float se[HIDDEN];
    se[t] = e;
    if (write_emb) out[emb_off + g * HIDDEN + t] = e;
    __syncthreads();
    if (write_logits && t < NUM_CLASSES) {
        float acc = linb[t];
#pragma unroll 16
        for (int k = 0; k < HIDDEN; k++)
            acc += se[k] * linW[k * NUM_CLASSES + t];
        out[g * NUM_CLASSES + t] = acc;
    }
}

extern "C" void kernel_launch(void* const* d_in, const int* in_sizes, int n_in,
                              void* d_out, int out_size) {
    const float* x     = (const float*)d_in[0];
    const int*   ei    = (const int*)d_in[1];   // [2, E] (JAX x64 off -> int32)
    const int*   batch = (const int*)d_in[2];
    const float* W0 = (const float*)d_in[3];
    const float* b0 = (const float*)d_in[4];
    const float* W1 = (const float*)d_in[5];
    const float* b1 = (const float*)d_in[6];
    const float* W2 = (const float*)d_in[7];
    const float* b2 = (const float*)d_in[8];
    const float* linW = (const float*)d_in[9];
    const float* linb = (const float*)d_in[10];
    float* out = (float*)d_out;

    const int* src = ei;            // edge_index[0]
    const int* dst = ei + N_EDGES;  // edge_index[1]

    // ---- input conversions + CSR build (once per launch) ----
    k_cvt_x<<<(N_NODES * (HIDDEN / 2) + 255) / 256, 256>>>(x);
    k_cvt_w<<<(HIDDEN * HIDDEN + 255) / 256, 256>>>(W0, W1, W2);
    k_zero<<<(N_NODES + 255) / 256, 256>>>();
    k_deg<<<(N_EDGES + 255) / 256, 256>>>(dst);
    k_scan1<<<SCAN_NBLK, SCAN_BLK>>>();
    k_scan2<<<1, SCAN_BLK>>>();
    k_scan3<<<SCAN_NBLK, SCAN_BLK>>>();
    k_fill<<<(N_EDGES + 255) / 256, 256>>>(src, dst);

    const float* bs[3] = {b0, b1, b2};
    const int gemm_grid = (N_NODES + TC_ROWS - 1) / TC_ROWS;   // 782
    const int agg_grid = N_NODES / AGG_NODES;                  // 12500 exact

    for (int l = 0; l < 3; l++) {
        k_gemm_tc<<<gemm_grid, 256>>>(l);
        k_agg<<<agg_grid, 256>>>(bs[l]);
    }

    k_pool<<<(N_NODES + NODES_PER_BLOCK - 1) / NODES_PER_BLOCK, 64>>>(batch);

    // Output: reference returns (logits[64,6], embedding[64,128]) -> 8576 floats.
    int write_logits = 1, write_emb = 0, emb_off = 0;
    if (out_size >= NUM_GRAPHS * (NUM_CLASSES + HIDDEN)) {
        write_emb = 1; emb_off = NUM_GRAPHS * NUM_CLASSES;
    } else if (out_size == NUM_GRAPHS * HIDDEN) {
        write_emb = 1; write_logits = 0; emb_off = 0;
    }
    k_final<<<NUM_GRAPHS, HIDDEN>>>(linW, linb, out, emb_off, write_emb, write_logits);
}